// round 6
// baseline (speedup 1.0000x reference)
#include <cuda_runtime.h>

#define NPTS 1024

// ---------------- packed f32x2 helpers (Blackwell) ----------------
static __device__ __forceinline__ unsigned long long pack2(float lo, float hi) {
    unsigned long long r;
    asm("mov.b64 %0, {%1,%2};" : "=l"(r) : "f"(lo), "f"(hi));
    return r;
}
static __device__ __forceinline__ float2 unpack2(unsigned long long v) {
    float2 r;
    asm("mov.b64 {%0,%1}, %2;" : "=f"(r.x), "=f"(r.y) : "l"(v));
    return r;
}
static __device__ __forceinline__ void fma2(unsigned long long& d,
                                            unsigned long long a,
                                            unsigned long long b) {
    asm("fma.rn.f32x2 %0, %1, %2, %0;" : "+l"(d) : "l"(a), "l"(b));
}

// pooled[i][o] intermediate (device-global scratch; no allocations allowed)
__device__ float g_pooled[NPTS * 128];

// ============================================================================
// Kernel A: sparse per-pair MLP (5 -> 64 -> 128) + masked max-pool.
// 16-neighbor groups, ONE barrier per group (was 2 per 8-nbr group):
//   - h1 double-buffered: conv1(g+1) writes h1[b^1] while conv2(g) read h1[b]
//   - partials pipelined: half1 publishes to part[b]; half0 carries its sums
//     in registers and combines the PREVIOUS group after the barrier.
// Thread = (ch-pair p, k-half, nnset of 8 neighbors).
// ============================================================================
__global__ __launch_bounds__(256, 2) void pool_kernel(
    const float* __restrict__ s,
    const float* __restrict__ w1g, const float* __restrict__ b1g,
    const float* __restrict__ w2g, const float* __restrict__ b2g)
{
    __shared__ __align__(16) float4 s4[NPTS];        // 16KB
    __shared__ int   nbr[NPTS];                      // 4KB
    __shared__ __align__(16) float h1[2][16 * 64];   // 8KB  (double-buffered)
    __shared__ float part[2][16][128];               // 16KB (double-buffered)
    __shared__ float w1s[64 * 5];
    __shared__ float b1s[64];
    __shared__ int cnt, cntp;

    const int tid   = threadIdx.x;
    const int p     = tid & 63;         // channel pair: ch {p, p+64}
    const int half  = (tid >> 6) & 1;   // k-half
    const int nnset = tid >> 7;         // neighbor subset: nn in [nnset*8, +8)

    // ---- conv2 weights for 2 channels x 32 k's: 16 LDG.128, 32 f32x2 packs ----
    unsigned long long w2p[2][16];
    float b2r[2];
#pragma unroll
    for (int c = 0; c < 2; c++) {
        int ch = p + 64 * c;
        const float4* wr = reinterpret_cast<const float4*>(w2g + ch * 64 + half * 32);
        float4 wv[8];
#pragma unroll
        for (int q = 0; q < 8; q++) wv[q] = wr[q];
#pragma unroll
        for (int q = 0; q < 8; q++) {
            w2p[c][2 * q]     = pack2(wv[q].x, wv[q].y);
            w2p[c][2 * q + 1] = pack2(wv[q].z, wv[q].w);
        }
        b2r[c] = b2g[ch];
    }

    // ---- stage s (4 batched LDG.128 each), w1, b1 ----
#pragma unroll
    for (int j = 0; j < 4; j++)
        s4[tid + 256 * j] = reinterpret_cast<const float4*>(s)[tid + 256 * j];
    for (int idx = tid; idx < 320; idx += 256) w1s[idx] = w1g[idx];
    if (tid < 64) b1s[tid] = b1g[tid];
    if (tid == 0) cnt = 0;
    __syncthreads();

    const int   c1 = tid & 63;   // conv1 channel this thread computes
    const int   g4 = tid >> 6;   // conv1 slot base: slots {g4, g4+4, g4+8, g4+12}
    const float w1r0 = w1s[c1 * 5 + 0], w1r1 = w1s[c1 * 5 + 1],
                w1r2 = w1s[c1 * 5 + 2], w1r3 = w1s[c1 * 5 + 3],
                w1r4 = w1s[c1 * 5 + 4], b1r = b1s[c1];

    const int i = blockIdx.x;
    const float4 si = s4[i];

    // ---- neighbor scan: dx^2+dy^2 < 0.25 (== dist < 0.5; self passes) ----
    for (int j = tid; j < NPTS; j += 256) {
        float4 sj = s4[j];
        float dx = si.x - sj.x, dy = si.y - sj.y;
        if (dx * dx + dy * dy < 0.25f) {
            int pq = atomicAdd(&cnt, 1);
            nbr[pq] = j;
        }
    }
    __syncthreads();
    if (tid == 0) {
        int c = cnt, cp = (c + 15) & ~15;
        for (int t = c; t < cp; t++) nbr[t] = i;  // pad with self (idempotent under max)
        cntp = cp;
    }
    __syncthreads();
    const int cp = cntp;

    float pooled[2] = {0.0f, 0.0f};  // max vs 0 covers mask zeros & relu
    float psum[2][8];                // half0's carried partial sums (prev group)
    int b = 0;

    for (int n = 0; n < cp; n += 16, b ^= 1) {
        // conv1: thread fills h1[b] for slots {g4, g4+4, g4+8, g4+12}
#pragma unroll
        for (int t = 0; t < 4; t++) {
            int sl = g4 + 4 * t;
            int j  = nbr[n + sl];
            float4 sj = s4[j];
            float dx = si.x - sj.x, dy = si.y - sj.y;
            float dz = si.z - sj.z, dw = si.w - sj.w;
            float ind = (j == i) ? 1.0f : 0.0f;
            float v = b1r;
            v = fmaf(dx, w1r0, v);
            v = fmaf(dy, w1r1, v);
            v = fmaf(dz, w1r2, v);
            v = fmaf(dw, w1r3, v);
            v = fmaf(ind, w1r4, v);
            h1[b][sl * 64 + c1] = fmaxf(v, 0.0f);   // lane-consecutive: conflict-free
        }
        __syncthreads();   // h1[b] ready; part[b^1] (prev group) visible

        // combine PREVIOUS group (half0 warps only; whole-warp uniform)
        if (n > 0 && half == 0) {
            int pb = b ^ 1;
#pragma unroll
            for (int t = 0; t < 8; t++) {
                int nn = nnset * 8 + t;
                pooled[0] = fmaxf(pooled[0], psum[0][t] + part[pb][nn][p]      + b2r[0]);
                pooled[1] = fmaxf(pooled[1], psum[1][t] + part[pb][nn][p + 64] + b2r[1]);
            }
        }

        // conv2: 8 neighbors (this nnset) x 2 ch x 32 k, two passes of 4 nbr
#pragma unroll
        for (int pass = 0; pass < 2; pass++) {
            unsigned long long acc[2][4];
#pragma unroll
            for (int t = 0; t < 4; t++) { acc[0][t] = 0ull; acc[1][t] = 0ull; }
#pragma unroll
            for (int t = 0; t < 4; t++) {
                int nn = nnset * 8 + pass * 4 + t;
                const ulonglong2* hb = reinterpret_cast<const ulonglong2*>(
                    &h1[b][nn * 64 + half * 32]);
#pragma unroll
                for (int q = 0; q < 8; q++) {
                    ulonglong2 hp = hb[q];            // LDS.128 broadcast
                    fma2(acc[0][t], hp.x, w2p[0][2 * q]);
                    fma2(acc[0][t], hp.y, w2p[0][2 * q + 1]);
                    fma2(acc[1][t], hp.x, w2p[1][2 * q]);
                    fma2(acc[1][t], hp.y, w2p[1][2 * q + 1]);
                }
            }
#pragma unroll
            for (int t = 0; t < 4; t++) {
                int nn = nnset * 8 + pass * 4 + t;
                float2 f0 = unpack2(acc[0][t]);
                float2 f1 = unpack2(acc[1][t]);
                float s0 = f0.x + f0.y, s1 = f1.x + f1.y;
                if (half == 1) {
                    part[b][nn][p]      = s0;         // publish k-half 1
                    part[b][nn][p + 64] = s1;
                } else {
                    psum[0][pass * 4 + t] = s0;       // carry k-half 0 in regs
                    psum[1][pass * 4 + t] = s1;
                }
            }
        }
    }

    // drain: combine the last group (its buffer is b^1 after the final toggle)
    __syncthreads();
    if (half == 0) {
        int pb = b ^ 1;
#pragma unroll
        for (int t = 0; t < 8; t++) {
            int nn = nnset * 8 + t;
            pooled[0] = fmaxf(pooled[0], psum[0][t] + part[pb][nn][p]      + b2r[0]);
            pooled[1] = fmaxf(pooled[1], psum[1][t] + part[pb][nn][p + 64] + b2r[1]);
        }
    }

    // reduce across nnset (2 half0 threads per channel)
    __syncthreads();
    if (half == 0 && nnset == 1) {
        part[0][0][p] = pooled[0];
        part[0][1][p] = pooled[1];
    }
    __syncthreads();
    if (half == 0 && nnset == 0) {
        g_pooled[i * 128 + p]      = fmaxf(pooled[0], part[0][0][p]);
        g_pooled[i * 128 + p + 64] = fmaxf(pooled[1], part[0][1][p]);
    }
}

// ============================================================================
// Kernel B: trunk  feat[132] -> 64 -> 128 -> 64 -> 4 -> (a_x, a_y)
// 256 blocks x 256 threads, 4 rows/block (warps 0-3 compute, all 8 stage).
// Weights staged as k-pair u64 (transposed, odd u64 pitch); GEMV via f32x2.
// ============================================================================
__global__ __launch_bounds__(256) void trunk_kernel(
    const float* __restrict__ s, const float* __restrict__ g,
    const float* __restrict__ fc1w, const float* __restrict__ fc1b,
    const float* __restrict__ fc2w, const float* __restrict__ fc2b,
    const float* __restrict__ fc3w, const float* __restrict__ fc3b,
    const float* __restrict__ fc4w, const float* __restrict__ fc4b,
    float* __restrict__ out)
{
    __shared__ unsigned long long wP[66 * 65];   // 34.3KB, reused per layer
    __shared__ float w4[64 * 4];
    __shared__ float bb1[64], bb2[128], bb3[64], b4s[4];
    __shared__ __align__(16) float act[4][132];

    const int tid    = threadIdx.x;
    const int lane   = tid & 31;
    const int w      = tid >> 5;
    const bool active = (w < 4);
    const int r      = blockIdx.x * 4 + (active ? w : 0);

    float4 sv = make_float4(0.f, 0.f, 0.f, 0.f);
    float2 gv = make_float2(0.f, 0.f);
    if (active) {
        sv = reinterpret_cast<const float4*>(s)[r];
        gv = reinterpret_cast<const float2*>(g)[r];
    }

    // ---- fc1 staging loads: 2112 float4, register-buffered (MLP 8-9) ----
    const float4* f1w4 = reinterpret_cast<const float4*>(fc1w);
    float4 v1[8];
#pragma unroll
    for (int rr = 0; rr < 8; rr++) v1[rr] = f1w4[tid + 256 * rr];
    float4 v1x;
    if (tid < 64) v1x = f1w4[2048 + tid];

    // feat = [pooled(128), s0-g0, s1-g1, s2, s3]
    if (active) {
#pragma unroll
        for (int j = 0; j < 4; j++)
            act[w][lane + 32 * j] = g_pooled[r * 128 + lane + 32 * j];
        if (lane == 0) {
            act[w][128] = sv.x - gv.x;
            act[w][129] = sv.y - gv.y;
            act[w][130] = sv.z;
            act[w][131] = sv.w;
        }
    }

    // biases + fc4
    if (tid < 64)  bb1[tid] = fc1b[tid];
    if (tid < 128) bb2[tid] = fc2b[tid];
    if (tid >= 128 && tid < 192) bb3[tid - 128] = fc3b[tid - 128];
    if (tid < 4)   b4s[tid] = fc4b[tid];
    if (tid < 64) {                       // fc4: 64 float4s
        float4 v = reinterpret_cast<const float4*>(fc4w)[tid];
        int o = tid >> 4;
        int k = (tid << 2) & 63;
        w4[(k + 0) * 4 + o] = v.x; w4[(k + 1) * 4 + o] = v.y;
        w4[(k + 2) * 4 + o] = v.z; w4[(k + 3) * 4 + o] = v.w;
    }

    // ---- STS fc1 as k-pair u64: wP[k2*65 + o] ----
#pragma unroll
    for (int rr = 0; rr < 8; rr++) {
        int e = (tid + 256 * rr) << 2;
        int o = e / 132;                  // 132 % 4 == 0: no row straddle
        int k = e - o * 132;
        int k2 = k >> 1;
        wP[(k2 + 0) * 65 + o] = pack2(v1[rr].x, v1[rr].y);
        wP[(k2 + 1) * 65 + o] = pack2(v1[rr].z, v1[rr].w);
    }
    if (tid < 64) {
        int e = (2048 + tid) << 2;
        int o = e / 132;
        int k = e - o * 132;
        int k2 = k >> 1;
        wP[(k2 + 0) * 65 + o] = pack2(v1x.x, v1x.y);
        wP[(k2 + 1) * 65 + o] = pack2(v1x.z, v1x.w);
    }
    __syncthreads();

    // prefetch fc2 (2048 float4) before L1 compute
    const float4* f2w4 = reinterpret_cast<const float4*>(fc2w);
    float4 v2[8];
#pragma unroll
    for (int rr = 0; rr < 8; rr++) v2[rr] = f2w4[tid + 256 * rr];

    // L1: 132 -> 64 via f32x2 pairs
    {
        float a0 = 0.f, a1 = 0.f;
        if (active) {
            const unsigned long long* actp =
                reinterpret_cast<const unsigned long long*>(act[w]);
            unsigned long long a0p = 0ull, a1p = 0ull;
#pragma unroll 6
            for (int k2 = 0; k2 < 66; k2++) {
                unsigned long long ap = actp[k2];
                fma2(a0p, ap, wP[k2 * 65 + lane]);
                fma2(a1p, ap, wP[k2 * 65 + lane + 32]);
            }
            float2 f0 = unpack2(a0p), f1 = unpack2(a1p);
            a0 = fmaxf(f0.x + f0.y + bb1[lane], 0.0f);
            a1 = fmaxf(f1.x + f1.y + bb1[lane + 32], 0.0f);
        }
        __syncthreads();                  // everyone done with fc1 weights
        if (active) { act[w][lane] = a0; act[w][lane + 32] = a1; }
    }

    // ---- STS fc2: [128][64] -> wP[k2*129 + o] ----
#pragma unroll
    for (int rr = 0; rr < 8; rr++) {
        int e = (tid + 256 * rr) << 2;
        int o = e >> 6;
        int k = e & 63;
        int k2 = k >> 1;
        wP[(k2 + 0) * 129 + o] = pack2(v2[rr].x, v2[rr].y);
        wP[(k2 + 1) * 129 + o] = pack2(v2[rr].z, v2[rr].w);
    }
    __syncthreads();

    // prefetch fc3 before L2 compute
    const float4* f3w4 = reinterpret_cast<const float4*>(fc3w);
    float4 v3[8];
#pragma unroll
    for (int rr = 0; rr < 8; rr++) v3[rr] = f3w4[tid + 256 * rr];

    // L2: 64 -> 128
    {
        float o0 = 0.f, o1 = 0.f, o2 = 0.f, o3 = 0.f;
        if (active) {
            const unsigned long long* actp =
                reinterpret_cast<const unsigned long long*>(act[w]);
            unsigned long long ac[4] = {0ull, 0ull, 0ull, 0ull};
#pragma unroll 4
            for (int k2 = 0; k2 < 32; k2++) {
                unsigned long long ap = actp[k2];
                fma2(ac[0], ap, wP[k2 * 129 + lane]);
                fma2(ac[1], ap, wP[k2 * 129 + lane + 32]);
                fma2(ac[2], ap, wP[k2 * 129 + lane + 64]);
                fma2(ac[3], ap, wP[k2 * 129 + lane + 96]);
            }
            { float2 f = unpack2(ac[0]); o0 = fmaxf(f.x + f.y + bb2[lane],      0.0f); }
            { float2 f = unpack2(ac[1]); o1 = fmaxf(f.x + f.y + bb2[lane + 32], 0.0f); }
            { float2 f = unpack2(ac[2]); o2 = fmaxf(f.x + f.y + bb2[lane + 64], 0.0f); }
            { float2 f = unpack2(ac[3]); o3 = fmaxf(f.x + f.y + bb2[lane + 96], 0.0f); }
        }
        __syncthreads();
        if (active) {
            act[w][lane] = o0; act[w][lane + 32] = o1;
            act[w][lane + 64] = o2; act[w][lane + 96] = o3;
        }
    }

    // ---- STS fc3: [64][128] -> wP[k2*65 + o] ----
#pragma unroll
    for (int rr = 0; rr < 8; rr++) {
        int e = (tid + 256 * rr) << 2;
        int o = e >> 7;
        int k = e & 127;
        int k2 = k >> 1;
        wP[(k2 + 0) * 65 + o] = pack2(v3[rr].x, v3[rr].y);
        wP[(k2 + 1) * 65 + o] = pack2(v3[rr].z, v3[rr].w);
    }
    __syncthreads();

    if (active) {
        // L3: 128 -> 64 (warp-private from here on)
        const unsigned long long* actp =
            reinterpret_cast<const unsigned long long*>(act[w]);
        unsigned long long a0p = 0ull, a1p = 0ull;
#pragma unroll 8
        for (int k2 = 0; k2 < 64; k2++) {
            unsigned long long ap = actp[k2];
            fma2(a0p, ap, wP[k2 * 65 + lane]);
            fma2(a1p, ap, wP[k2 * 65 + lane + 32]);
        }
        float2 f0 = unpack2(a0p), f1 = unpack2(a1p);
        float a0 = fmaxf(f0.x + f0.y + bb3[lane], 0.0f);
        float a1 = fmaxf(f1.x + f1.y + bb3[lane + 32], 0.0f);
        __syncwarp();
        act[w][lane] = a0; act[w][lane + 32] = a1;
        __syncwarp();

        // L4: 64 -> 4, sigmoid, gains (per warp)
        int ol = lane & 3;
        float acc = b4s[ol];
#pragma unroll 4
        for (int k = 0; k < 64; k++)
            acc = fmaf(act[w][k], w4[k * 4 + ol], acc);
        float kv = 2.0f / (1.0f + expf(-acc)) - 1.0f;

        float k1 = __shfl_sync(0xffffffffu, kv, 0);
        float k2 = __shfl_sync(0xffffffffu, kv, 1);
        float k3 = __shfl_sync(0xffffffffu, kv, 2);
        float k4 = __shfl_sync(0xffffffffu, kv, 3);

        if (lane == 0) {
            float sg0 = sv.x - gv.x;
            float sg1 = sv.y - gv.y;
            out[r * 2 + 0] = -(k1 * sg0 + k2 * sv.z);
            out[r * 2 + 1] = -(k3 * sg1 + k4 * sv.w);
        }
    }
}

// ============================================================================
extern "C" void kernel_launch(void* const* d_in, const int* in_sizes, int n_in,
                              void* d_out, int out_size)
{
    const float* s    = (const float*)d_in[0];
    const float* g    = (const float*)d_in[1];
    const float* c1w  = (const float*)d_in[2];
    const float* c1b  = (const float*)d_in[3];
    const float* c2w  = (const float*)d_in[4];
    const float* c2b  = (const float*)d_in[5];
    const float* f1w  = (const float*)d_in[6];
    const float* f1b  = (const float*)d_in[7];
    const float* f2w  = (const float*)d_in[8];
    const float* f2b  = (const float*)d_in[9];
    const float* f3w  = (const float*)d_in[10];
    const float* f3b  = (const float*)d_in[11];
    const float* f4w  = (const float*)d_in[12];
    const float* f4b  = (const float*)d_in[13];
    float* out = (float*)d_out;

    pool_kernel<<<NPTS, 256>>>(s, c1w, c1b, c2w, c2b);
    trunk_kernel<<<NPTS / 4, 256>>>(s, g, f1w, f1b, f2w, f2b, f3w, f3b,
                                    f4w, f4b, out);
}

// round 7
// speedup vs baseline: 1.0597x; 1.0597x over previous
#include <cuda_runtime.h>

#define NPTS 1024

// ---------------- packed f32x2 helpers (Blackwell) ----------------
static __device__ __forceinline__ unsigned long long pack2(float lo, float hi) {
    unsigned long long r;
    asm("mov.b64 %0, {%1,%2};" : "=l"(r) : "f"(lo), "f"(hi));
    return r;
}
static __device__ __forceinline__ float2 unpack2(unsigned long long v) {
    float2 r;
    asm("mov.b64 {%0,%1}, %2;" : "=f"(r.x), "=f"(r.y) : "l"(v));
    return r;
}
static __device__ __forceinline__ void fma2(unsigned long long& d,
                                            unsigned long long a,
                                            unsigned long long b) {
    asm("fma.rn.f32x2 %0, %1, %2, %0;" : "+l"(d) : "l"(a), "l"(b));
}

// ============================================================================
// Fused kernel: 256 blocks x 256 threads; block b owns rows 4b..4b+3.
// Phase P: sparse pair-MLP (5->64->128) + masked max-pool for 4 rows
//          (one s-staging + one scan + one weight-load serves all 4 rows).
// Phase T: trunk feat[132]->64->128->64->4 -> (a_x,a_y) for the same 4 rows.
// Shared memory is a phase-overlaid pool; feat[] carries P->T.
// ============================================================================

// ---- shared memory layout (bytes) ----
// Phase P:  s4 @0 [16384] | nbr @16384 [4][256]*4B | h1 @20480 [8*64]*4B
//           part @22528 [8][128]*4B | w1s @26624 [320]*4B | b1s @27904 [64]*4B
// Phase T:  wP @0 u64[66*65]=34320 | w4 @34320 [256]*4B | bb1 @35344 |
//           bb2 @35600 | bb3 @36112 | b4s @36368
// Persist:  feat @36384 [4][132]*4B | cnt @38496 int[8]
#define SM_TOTAL 38528

__global__ __launch_bounds__(256, 2) void fused_kernel(
    const float* __restrict__ s, const float* __restrict__ g,
    const float* __restrict__ w1g, const float* __restrict__ b1g,
    const float* __restrict__ w2g, const float* __restrict__ b2g,
    const float* __restrict__ fc1w, const float* __restrict__ fc1b,
    const float* __restrict__ fc2w, const float* __restrict__ fc2b,
    const float* __restrict__ fc3w, const float* __restrict__ fc3b,
    const float* __restrict__ fc4w, const float* __restrict__ fc4b,
    float* __restrict__ out)
{
    __shared__ __align__(16) char smem_raw[SM_TOTAL];

    const int tid = threadIdx.x;

    // ======================= PHASE P: pool =======================
    float4* s4   = reinterpret_cast<float4*>(smem_raw);
    int (*nbr)[256] = reinterpret_cast<int(*)[256]>(smem_raw + 16384);
    float* h1    = reinterpret_cast<float*>(smem_raw + 20480);
    float (*part)[128] = reinterpret_cast<float(*)[128]>(smem_raw + 22528);
    float* w1s   = reinterpret_cast<float*>(smem_raw + 26624);
    float* b1s   = reinterpret_cast<float*>(smem_raw + 27904);
    float (*feat)[132] = reinterpret_cast<float(*)[132]>(smem_raw + 36384);
    int*   cnt   = reinterpret_cast<int*>(smem_raw + 38496);
    int*   cntp  = cnt + 4;

    const int p     = tid & 63;         // channel pair: ch {p, p+64}
    const int half  = (tid >> 6) & 1;   // k-half
    const int nnset = tid >> 7;         // neighbor subset (4 of 8 per group)

    // conv2 weights for 2 channels x 32 k's: 16 LDG.128 -> 32 f32x2 packs
    unsigned long long w2p[2][16];
    float b2r[2];
#pragma unroll
    for (int c = 0; c < 2; c++) {
        int ch = p + 64 * c;
        const float4* wr = reinterpret_cast<const float4*>(w2g + ch * 64 + half * 32);
        float4 wv[8];
#pragma unroll
        for (int q = 0; q < 8; q++) wv[q] = wr[q];
#pragma unroll
        for (int q = 0; q < 8; q++) {
            w2p[c][2 * q]     = pack2(wv[q].x, wv[q].y);
            w2p[c][2 * q + 1] = pack2(wv[q].z, wv[q].w);
        }
        b2r[c] = b2g[ch];
    }

    // stage s (4 batched LDG.128 each), w1, b1; reset counters
#pragma unroll
    for (int j = 0; j < 4; j++)
        s4[tid + 256 * j] = reinterpret_cast<const float4*>(s)[tid + 256 * j];
    for (int idx = tid; idx < 320; idx += 256) w1s[idx] = w1g[idx];
    if (tid < 64) b1s[tid] = b1g[tid];
    if (tid < 4)  cnt[tid] = 0;
    __syncthreads();

    const int   c1  = tid & 63;   // conv1 channel this thread computes
    const int   slb = tid >> 6;   // conv1 slot base (covers slb, slb+4)
    const float w1r0 = w1s[c1 * 5 + 0], w1r1 = w1s[c1 * 5 + 1],
                w1r2 = w1s[c1 * 5 + 2], w1r3 = w1s[c1 * 5 + 3],
                w1r4 = w1s[c1 * 5 + 4], b1r = b1s[c1];

    const int i0 = blockIdx.x * 4;
    float4 si[4];
#pragma unroll
    for (int rr = 0; rr < 4; rr++) si[rr] = s4[i0 + rr];

    // ---- one scan pass serves all 4 rows ----
    for (int j = tid; j < NPTS; j += 256) {
        float4 sj = s4[j];
#pragma unroll
        for (int rr = 0; rr < 4; rr++) {
            float dx = si[rr].x - sj.x, dy = si[rr].y - sj.y;
            if (dx * dx + dy * dy < 0.25f) {
                int pq = atomicAdd(&cnt[rr], 1);
                nbr[rr][pq] = j;
            }
        }
    }
    __syncthreads();
    if (tid < 4) {
        int c = cnt[tid], cp = (c + 7) & ~7;
        for (int t = c; t < cp; t++) nbr[tid][t] = i0 + tid;  // self-pad (idempotent)
        cntp[tid] = cp;
    }
    __syncthreads();

    // ---- per-row pool ----
    for (int rr = 0; rr < 4; rr++) {
        const float4 sir = si[rr];
        const int    i   = i0 + rr;
        const int    cp  = cntp[rr];
        const int*   nb  = nbr[rr];

        float pooled0 = 0.0f, pooled1 = 0.0f;  // max vs 0 covers mask & relu

        for (int n = 0; n < cp; n += 8) {
            // conv1: thread fills h1[c1] for slots slb and slb+4
#pragma unroll
            for (int t = 0; t < 2; t++) {
                int sl = slb + 4 * t;
                int j  = nb[n + sl];
                float4 sj = s4[j];
                float dx = sir.x - sj.x, dy = sir.y - sj.y;
                float dz = sir.z - sj.z, dw = sir.w - sj.w;
                float ind = (j == i) ? 1.0f : 0.0f;
                float v = b1r;
                v = fmaf(dx, w1r0, v);
                v = fmaf(dy, w1r1, v);
                v = fmaf(dz, w1r2, v);
                v = fmaf(dw, w1r3, v);
                v = fmaf(ind, w1r4, v);
                h1[sl * 64 + c1] = fmaxf(v, 0.0f);   // conflict-free
            }
            __syncthreads();

            // conv2: 4 neighbors x 2 channels x 32 k; 1 LDS.128 feeds 4 fma2
            unsigned long long acc[2][4];
#pragma unroll
            for (int t = 0; t < 4; t++) { acc[0][t] = 0ull; acc[1][t] = 0ull; }
#pragma unroll
            for (int t = 0; t < 4; t++) {
                const ulonglong2* hb = reinterpret_cast<const ulonglong2*>(
                    h1 + (nnset * 4 + t) * 64 + half * 32);
#pragma unroll
                for (int q = 0; q < 8; q++) {
                    ulonglong2 hp = hb[q];            // LDS.128 broadcast
                    fma2(acc[0][t], hp.x, w2p[0][2 * q]);
                    fma2(acc[0][t], hp.y, w2p[0][2 * q + 1]);
                    fma2(acc[1][t], hp.x, w2p[1][2 * q]);
                    fma2(acc[1][t], hp.y, w2p[1][2 * q + 1]);
                }
            }

            if (half == 1) {
#pragma unroll
                for (int t = 0; t < 4; t++) {
                    int nn = nnset * 4 + t;
                    float2 f0 = unpack2(acc[0][t]);
                    float2 f1 = unpack2(acc[1][t]);
                    part[nn][p]      = f0.x + f0.y;
                    part[nn][p + 64] = f1.x + f1.y;
                }
            }
            __syncthreads();
            if (half == 0) {
#pragma unroll
                for (int t = 0; t < 4; t++) {
                    int nn = nnset * 4 + t;
                    float2 f0 = unpack2(acc[0][t]);
                    float2 f1 = unpack2(acc[1][t]);
                    pooled0 = fmaxf(pooled0, f0.x + f0.y + part[nn][p]      + b2r[0]);
                    pooled1 = fmaxf(pooled1, f1.x + f1.y + part[nn][p + 64] + b2r[1]);
                }
            }
            // safe: half1's next part writes occur after the next post-conv1
            // barrier, which half0 reaches only after these combines.
        }

        // cross-nnset reduce -> feat[rr]
        __syncthreads();
        if (half == 0 && nnset == 1) {
            part[0][p] = pooled0;
            part[1][p] = pooled1;
        }
        __syncthreads();
        if (half == 0 && nnset == 0) {
            feat[rr][p]      = fmaxf(pooled0, part[0][p]);
            feat[rr][p + 64] = fmaxf(pooled1, part[1][p]);
        }
        // feat writes complete before the next row's post-conv1 barrier,
        // after which part may be overwritten.
    }
    __syncthreads();   // P-phase smem dead; safe to overlay T-phase data

    // ======================= PHASE T: trunk =======================
    unsigned long long* wP = reinterpret_cast<unsigned long long*>(smem_raw);
    float* w4  = reinterpret_cast<float*>(smem_raw + 34320);
    float* bb1 = reinterpret_cast<float*>(smem_raw + 35344);
    float* bb2 = reinterpret_cast<float*>(smem_raw + 35600);
    float* bb3 = reinterpret_cast<float*>(smem_raw + 36112);
    float* b4s = reinterpret_cast<float*>(smem_raw + 36368);
    float (*act)[132] = feat;   // same storage

    const int lane   = tid & 31;
    const int w      = tid >> 5;
    const bool active = (w < 4);
    const int r      = i0 + (active ? w : 0);

    float4 sv = make_float4(0.f, 0.f, 0.f, 0.f);
    float2 gv = make_float2(0.f, 0.f);
    if (active) {
        sv = reinterpret_cast<const float4*>(s)[r];
        gv = reinterpret_cast<const float2*>(g)[r];
        if (lane == 0) {
            act[w][128] = sv.x - gv.x;
            act[w][129] = sv.y - gv.y;
            act[w][130] = sv.z;
            act[w][131] = sv.w;
        }
    }

    // fc1 staging loads: 2112 float4, register-buffered
    const float4* f1w4 = reinterpret_cast<const float4*>(fc1w);
    float4 v1[8];
#pragma unroll
    for (int rr = 0; rr < 8; rr++) v1[rr] = f1w4[tid + 256 * rr];
    float4 v1x;
    if (tid < 64) v1x = f1w4[2048 + tid];

    // biases + fc4
    if (tid < 64)  bb1[tid] = fc1b[tid];
    if (tid < 128) bb2[tid] = fc2b[tid];
    if (tid >= 128 && tid < 192) bb3[tid - 128] = fc3b[tid - 128];
    if (tid < 4)   b4s[tid] = fc4b[tid];
    if (tid < 64) {                       // fc4: 64 float4s
        float4 v = reinterpret_cast<const float4*>(fc4w)[tid];
        int o = tid >> 4;
        int k = (tid << 2) & 63;
        w4[(k + 0) * 4 + o] = v.x; w4[(k + 1) * 4 + o] = v.y;
        w4[(k + 2) * 4 + o] = v.z; w4[(k + 3) * 4 + o] = v.w;
    }

    // STS fc1 as k-pair u64: wP[k2*65 + o]
#pragma unroll
    for (int rr = 0; rr < 8; rr++) {
        int e = (tid + 256 * rr) << 2;
        int o = e / 132;                  // 132 % 4 == 0: no row straddle
        int k = e - o * 132;
        int k2 = k >> 1;
        wP[(k2 + 0) * 65 + o] = pack2(v1[rr].x, v1[rr].y);
        wP[(k2 + 1) * 65 + o] = pack2(v1[rr].z, v1[rr].w);
    }
    if (tid < 64) {
        int e = (2048 + tid) << 2;
        int o = e / 132;
        int k = e - o * 132;
        int k2 = k >> 1;
        wP[(k2 + 0) * 65 + o] = pack2(v1x.x, v1x.y);
        wP[(k2 + 1) * 65 + o] = pack2(v1x.z, v1x.w);
    }
    __syncthreads();

    // prefetch fc2 before L1 compute
    const float4* f2w4 = reinterpret_cast<const float4*>(fc2w);
    float4 v2[8];
#pragma unroll
    for (int rr = 0; rr < 8; rr++) v2[rr] = f2w4[tid + 256 * rr];

    // L1: 132 -> 64
    {
        float a0 = 0.f, a1 = 0.f;
        if (active) {
            const unsigned long long* actp =
                reinterpret_cast<const unsigned long long*>(act[w]);
            unsigned long long a0p = 0ull, a1p = 0ull;
#pragma unroll 6
            for (int k2 = 0; k2 < 66; k2++) {
                unsigned long long ap = actp[k2];
                fma2(a0p, ap, wP[k2 * 65 + lane]);
                fma2(a1p, ap, wP[k2 * 65 + lane + 32]);
            }
            float2 f0 = unpack2(a0p), f1 = unpack2(a1p);
            a0 = fmaxf(f0.x + f0.y + bb1[lane], 0.0f);
            a1 = fmaxf(f1.x + f1.y + bb1[lane + 32], 0.0f);
        }
        __syncthreads();
        if (active) { act[w][lane] = a0; act[w][lane + 32] = a1; }
    }

    // STS fc2: [128][64] -> wP[k2*129 + o]
#pragma unroll
    for (int rr = 0; rr < 8; rr++) {
        int e = (tid + 256 * rr) << 2;
        int o = e >> 6;
        int k = e & 63;
        int k2 = k >> 1;
        wP[(k2 + 0) * 129 + o] = pack2(v2[rr].x, v2[rr].y);
        wP[(k2 + 1) * 129 + o] = pack2(v2[rr].z, v2[rr].w);
    }
    __syncthreads();

    // prefetch fc3 before L2 compute
    const float4* f3w4 = reinterpret_cast<const float4*>(fc3w);
    float4 v3[8];
#pragma unroll
    for (int rr = 0; rr < 8; rr++) v3[rr] = f3w4[tid + 256 * rr];

    // L2: 64 -> 128
    {
        float o0 = 0.f, o1 = 0.f, o2 = 0.f, o3 = 0.f;
        if (active) {
            const unsigned long long* actp =
                reinterpret_cast<const unsigned long long*>(act[w]);
            unsigned long long ac[4] = {0ull, 0ull, 0ull, 0ull};
#pragma unroll 4
            for (int k2 = 0; k2 < 32; k2++) {
                unsigned long long ap = actp[k2];
                fma2(ac[0], ap, wP[k2 * 129 + lane]);
                fma2(ac[1], ap, wP[k2 * 129 + lane + 32]);
                fma2(ac[2], ap, wP[k2 * 129 + lane + 64]);
                fma2(ac[3], ap, wP[k2 * 129 + lane + 96]);
            }
            { float2 f = unpack2(ac[0]); o0 = fmaxf(f.x + f.y + bb2[lane],      0.0f); }
            { float2 f = unpack2(ac[1]); o1 = fmaxf(f.x + f.y + bb2[lane + 32], 0.0f); }
            { float2 f = unpack2(ac[2]); o2 = fmaxf(f.x + f.y + bb2[lane + 64], 0.0f); }
            { float2 f = unpack2(ac[3]); o3 = fmaxf(f.x + f.y + bb2[lane + 96], 0.0f); }
        }
        __syncthreads();
        if (active) {
            act[w][lane] = o0; act[w][lane + 32] = o1;
            act[w][lane + 64] = o2; act[w][lane + 96] = o3;
        }
    }

    // STS fc3: [64][128] -> wP[k2*65 + o]
#pragma unroll
    for (int rr = 0; rr < 8; rr++) {
        int e = (tid + 256 * rr) << 2;
        int o = e >> 7;
        int k = e & 127;
        int k2 = k >> 1;
        wP[(k2 + 0) * 65 + o] = pack2(v3[rr].x, v3[rr].y);
        wP[(k2 + 1) * 65 + o] = pack2(v3[rr].z, v3[rr].w);
    }
    __syncthreads();

    if (active) {
        // L3: 128 -> 64 (warp-private from here on)
        const unsigned long long* actp =
            reinterpret_cast<const unsigned long long*>(act[w]);
        unsigned long long a0p = 0ull, a1p = 0ull;
#pragma unroll 8
        for (int k2 = 0; k2 < 64; k2++) {
            unsigned long long ap = actp[k2];
            fma2(a0p, ap, wP[k2 * 65 + lane]);
            fma2(a1p, ap, wP[k2 * 65 + lane + 32]);
        }
        float2 f0 = unpack2(a0p), f1 = unpack2(a1p);
        float a0 = fmaxf(f0.x + f0.y + bb3[lane], 0.0f);
        float a1 = fmaxf(f1.x + f1.y + bb3[lane + 32], 0.0f);
        __syncwarp();
        act[w][lane] = a0; act[w][lane + 32] = a1;
        __syncwarp();

        // L4: 64 -> 4, sigmoid, gains
        int ol = lane & 3;
        float acc = b4s[ol];
#pragma unroll 4
        for (int k = 0; k < 64; k++)
            acc = fmaf(act[w][k], w4[k * 4 + ol], acc);
        float kv = 2.0f / (1.0f + expf(-acc)) - 1.0f;

        float k1 = __shfl_sync(0xffffffffu, kv, 0);
        float k2 = __shfl_sync(0xffffffffu, kv, 1);
        float k3 = __shfl_sync(0xffffffffu, kv, 2);
        float k4 = __shfl_sync(0xffffffffu, kv, 3);

        if (lane == 0) {
            float sg0 = sv.x - gv.x;
            float sg1 = sv.y - gv.y;
            out[r * 2 + 0] = -(k1 * sg0 + k2 * sv.z);
            out[r * 2 + 1] = -(k3 * sg1 + k4 * sv.w);
        }
    }
}

// ============================================================================
extern "C" void kernel_launch(void* const* d_in, const int* in_sizes, int n_in,
                              void* d_out, int out_size)
{
    const float* s    = (const float*)d_in[0];
    const float* g    = (const float*)d_in[1];
    const float* c1w  = (const float*)d_in[2];
    const float* c1b  = (const float*)d_in[3];
    const float* c2w  = (const float*)d_in[4];
    const float* c2b  = (const float*)d_in[5];
    const float* f1w  = (const float*)d_in[6];
    const float* f1b  = (const float*)d_in[7];
    const float* f2w  = (const float*)d_in[8];
    const float* f2b  = (const float*)d_in[9];
    const float* f3w  = (const float*)d_in[10];
    const float* f3b  = (const float*)d_in[11];
    const float* f4w  = (const float*)d_in[12];
    const float* f4b  = (const float*)d_in[13];
    float* out = (float*)d_out;

    fused_kernel<<<NPTS / 4, 256>>>(s, g, c1w, c1b, c2w, c2b,
                                    f1w, f1b, f2w, f2b, f3w, f3b,
                                    f4w, f4b, out);
}